// round 13
// baseline (speedup 1.0000x reference)
#include <cuda_runtime.h>
#include <cuda_fp16.h>
#include <math.h>
#include <cstdint>

#define BATCH 4096
#define SDIM  512
#define ADIM  64
#define HDIM  2048
#define KDIM  577
#define KP    576           // s(512) + a(64); reward column folded rank-1 in epilogue
#define NCH   9
#define FOURH 8192
#define VB_CH 64

// ---------------- scratch (static device globals) ----------------
__device__ __half g_x[BATCH * KP];      // fp16 packed [s|a]
__device__ __half g_w[FOURH * KP];      // gate-interleaved rows n' = j*4 + g, K-major
__device__ __half g_wa[64 * HDIM];      // Wa transposed [n][k] K-major fp16
__device__ float g_vbp[VB_CH * FOURH];  // k-split partials of h @ Wh
__device__ __half g_hf[BATCH * HDIM];   // h_new in fp16

__device__ __forceinline__ uint32_t smem_u32(const void* p) {
    uint32_t a;
    asm("{ .reg .u64 t; cvta.to.shared.u64 t, %1; cvt.u32.u64 %0, t; }" : "=r"(a) : "l"(p));
    return a;
}
#define SWZ128(off) ((off) ^ (((off) >> 3) & 0x70))

__device__ __forceinline__ void cpa16(uint32_t smem, const void* g) {
    asm volatile("cp.async.cg.shared.global [%0], [%1], 16;" :: "r"(smem), "l"(g));
}
#define CPA_COMMIT()  asm volatile("cp.async.commit_group;" ::: "memory")
#define CPA_WAIT(n)   asm volatile("cp.async.wait_group %0;" :: "n"(n) : "memory")

__device__ __forceinline__ void ldmx4(uint32_t* r, uint32_t addr) {
    asm volatile("ldmatrix.sync.aligned.m8n8.x4.shared.b16 {%0,%1,%2,%3}, [%4];"
                 : "=r"(r[0]), "=r"(r[1]), "=r"(r[2]), "=r"(r[3]) : "r"(addr));
}
__device__ __forceinline__ void ldmx2(uint32_t* r, uint32_t addr) {
    asm volatile("ldmatrix.sync.aligned.m8n8.x2.shared.b16 {%0,%1}, [%2];"
                 : "=r"(r[0]), "=r"(r[1]) : "r"(addr));
}
__device__ __forceinline__ void mma16816(float* c, const uint32_t* a, const uint32_t* b) {
    asm volatile(
        "mma.sync.aligned.m16n8k16.row.col.f32.f16.f16.f32 "
        "{%0,%1,%2,%3}, {%4,%5,%6,%7}, {%8,%9}, {%0,%1,%2,%3};"
        : "+f"(c[0]), "+f"(c[1]), "+f"(c[2]), "+f"(c[3])
        : "r"(a[0]), "r"(a[1]), "r"(a[2]), "r"(a[3]), "r"(b[0]), "r"(b[1]));
}

// fast gate math
__device__ __forceinline__ float fsig(float x) {
    return __fdividef(1.0f, 1.0f + __expf(-x));
}
__device__ __forceinline__ float ftanh(float x) {
    return 1.0f - __fdividef(2.0f, __expf(2.0f * x) + 1.0f);
}

// ---------------------------------------------------------------------------
// prep: fused vb_partial + convW + convA + convX (block-range dispatch)
//   [0, 2048)      vb_partial   (32 j-blocks x 64 k-chunks of 32)
//   [2048, 4352)   convW        (256 n-blocks x 9 k-blocks)
//   [4352, 4384)   convA        (32 k-blocks)
//   [4384, 5536)   convX        (1152 blocks, 8 halfs/thread)
// ---------------------------------------------------------------------------
#define PREP_BLOCKS 5536

__global__ __launch_bounds__(256) void prep(const float* __restrict__ s,
                                            const float* __restrict__ a,
                                            const float* __restrict__ h,
                                            const float* __restrict__ Wh,
                                            const float* __restrict__ Wx,
                                            const float* __restrict__ Wa) {
    __shared__ float t[64][65];
    int bid = blockIdx.x;
    int tid = threadIdx.x;

    if (bid < 2048) {
        // ---- vb_partial: 32-row k-chunks ----
        int j  = (bid & 31) * 256 + tid;
        int k0 = (bid >> 5) * 32;
        float acc = 0.0f;
#pragma unroll 16
        for (int k = 0; k < 32; k++)
            acc += h[k0 + k] * __ldg(&Wh[(size_t)(k0 + k) * FOURH + j]);
        g_vbp[(bid >> 5) * FOURH + j] = acc;
    } else if (bid < 4352) {
        // ---- convW ----
        int b  = bid - 2048;
        int n0 = (b & 255) * 32;
        int k0 = (b >> 8) * 64;
        int tx = tid & 31, ty = tid >> 5;
#pragma unroll
        for (int i = 0; i < 8; i++) {
            int kl = ty * 8 + i;
            t[kl][tx] = Wx[(size_t)(k0 + kl) * FOURH + n0 + tx];
        }
        __syncthreads();
        int nl = tid >> 3;
        int ch = tid & 7;
        int n  = n0 + nl;
        size_t np = (size_t)(n & 2047) * 4 + (n >> 11);
        uint4 vh;
        __half* ph = (__half*)&vh;
#pragma unroll
        for (int u = 0; u < 8; u++)
            ph[u] = __float2half_rn(t[ch * 8 + u][nl]);
        *(uint4*)&g_w[np * KP + k0 + ch * 8] = vh;
    } else if (bid < 4384) {
        // ---- convA ----
        int k0 = (bid - 4352) * 64;
#pragma unroll
        for (int i = 0; i < 16; i++) {
            int e = tid + i * 256;
            int kl = e >> 6, n = e & 63;
            t[kl][n] = Wa[(size_t)(k0 + kl) * 64 + n];
        }
        __syncthreads();
        int n = tid >> 2, kq = (tid & 3) * 16;
        uint4 v[2];
        __half* ph = (__half*)v;
#pragma unroll
        for (int u = 0; u < 16; u++)
            ph[u] = __float2half_rn(t[kq + u][n]);
        *(uint4*)&g_wa[(size_t)n * HDIM + k0 + kq]     = v[0];
        *(uint4*)&g_wa[(size_t)n * HDIM + k0 + kq + 8] = v[1];
    } else {
        // ---- convX ----
        int gid = (bid - 4384) * 256 + tid;
        int b = gid / 72, kc = gid - b * 72;
        int k0 = kc * 8;
        float4 f0, f1;
        if (k0 < SDIM) {
            f0 = *(const float4*)&s[(size_t)b * SDIM + k0];
            f1 = *(const float4*)&s[(size_t)b * SDIM + k0 + 4];
        } else {
            f0 = *(const float4*)&a[(size_t)b * ADIM + (k0 - SDIM)];
            f1 = *(const float4*)&a[(size_t)b * ADIM + (k0 - SDIM) + 4];
        }
        uint4 o;
        __half* ph = (__half*)&o;
        ph[0] = __float2half_rn(f0.x); ph[1] = __float2half_rn(f0.y);
        ph[2] = __float2half_rn(f0.z); ph[3] = __float2half_rn(f0.w);
        ph[4] = __float2half_rn(f1.x); ph[5] = __float2half_rn(f1.y);
        ph[6] = __float2half_rn(f1.z); ph[7] = __float2half_rn(f1.w);
        *(uint4*)&g_x[(size_t)b * KP + k0] = o;
    }
}

// ---------------------------------------------------------------------------
// lstm_mma: 4 warps (2x2), 64x64 per warp — halves A smem re-reads.
// ---------------------------------------------------------------------------
#define ST_A   0
#define ST_B   16384
#define ST_STRIDE 32768
#define SVB_OFF  (3 * ST_STRIDE)
#define SMEM_SZ  (3 * ST_STRIDE + 512)

__global__ __launch_bounds__(128, 2) void lstm_mma(const float* __restrict__ cvec,
                                                   const float* __restrict__ rp,
                                                   const float* __restrict__ w576,
                                                   const float* __restrict__ bh) {
    extern __shared__ char smem[];
    uint32_t sb = smem_u32(smem);
    int tid  = threadIdx.x;
    int lane = tid & 31, w = tid >> 5;
    int wm = w & 1, wn = w >> 1;          // 2 x 2 warp grid, 64x64 tiles
    int row0 = blockIdx.y * 128;
    int j0   = blockIdx.x * 32;

    int lr = lane & 7, ls = lane >> 3;
    uint32_t a_row = wm * 64 + lr + (ls & 1) * 8;   // + mt*16
    uint32_t a_chs = (uint32_t)(ls >> 1);
    uint32_t b_row = wn * 64 + lr;                  // + nt*8

    uint32_t pa0 = ST_A + (((a_row * 128) | ((a_row * 16) & 0x70)) ^ (a_chs << 4));
    uint32_t pb0 = ST_B + (((b_row * 128) | ((b_row * 16) & 0x70)) ^ ((uint32_t)ls << 4));

    uint32_t sw0 = SWZ128((uint32_t)((tid >> 3) * 128 + (tid & 7) * 16));
    const __half* px = g_x + (size_t)(row0 + (tid >> 3)) * KP + (tid & 7) * 8;
    const __half* pw = g_w + (size_t)(j0 * 4 + (tid >> 3)) * KP + (tid & 7) * 8;

    float acc[4][8][4];
#pragma unroll
    for (int mt = 0; mt < 4; mt++)
#pragma unroll
        for (int nt = 0; nt < 8; nt++)
#pragma unroll
            for (int i = 0; i < 4; i++) acc[mt][nt][i] = 0.0f;

#pragma unroll
    for (int st = 0; st < 2; st++) {      // prologue: chunks 0,1
        uint32_t base = sb + st * ST_STRIDE;
#pragma unroll
        for (int i = 0; i < 8; i++) {
            cpa16(base + ST_A + sw0 + i * 2048, px + (size_t)i * 16 * KP + st * 64);
            cpa16(base + ST_B + sw0 + i * 2048, pw + (size_t)i * 16 * KP + st * 64);
        }
        CPA_COMMIT();
    }

    // fused vb reduce (overlaps prologue cp.async)
    float* svb = (float*)(smem + SVB_OFF);
    {
        int j = (tid >> 5) * HDIM + j0 + (tid & 31);
        float acc_vb = __ldg(&bh[j]);
#pragma unroll
        for (int kc = 0; kc < VB_CH; kc++) acc_vb += g_vbp[kc * FOURH + j];
        svb[tid] = acc_vb;
    }

    for (int t = 0; t < NCH; t++) {
        if (t == NCH - 1) { CPA_WAIT(0); } else { CPA_WAIT(1); }
        __syncthreads();

        if (t + 2 < NCH) {
            uint32_t base = sb + ((t + 2) % 3) * ST_STRIDE;
            int kg = (t + 2) * 64;
#pragma unroll
            for (int i = 0; i < 8; i++) {
                cpa16(base + ST_A + sw0 + i * 2048, px + (size_t)i * 16 * KP + kg);
                cpa16(base + ST_B + sw0 + i * 2048, pw + (size_t)i * 16 * KP + kg);
            }
            CPA_COMMIT();
        }

        uint32_t sa = sb + (t % 3) * ST_STRIDE;
        uint32_t aA[4], aB[8];
#pragma unroll
        for (int mt = 0; mt < 4; mt++) aA[mt] = sa + pa0 + mt * 2048;
#pragma unroll
        for (int nt = 0; nt < 8; nt++) aB[nt] = sa + pb0 + nt * 1024;

#pragma unroll
        for (int half = 0; half < 2; half++) {
            uint32_t hoff = (uint32_t)(half << 6);
            uint32_t bb[8][4];                        // 8 n-frags x (2 ksteps x 2 regs)
#pragma unroll
            for (int nt = 0; nt < 8; nt++)
                ldmx4(bb[nt], aB[nt] ^ hoff);
#pragma unroll
            for (int ks = 0; ks < 2; ks++) {
                uint32_t koff = hoff + (uint32_t)(ks << 5);
#pragma unroll
                for (int mt = 0; mt < 4; mt++) {
                    uint32_t aa[4];
                    ldmx4(aa, aA[mt] ^ koff);
#pragma unroll
                    for (int nt = 0; nt < 8; nt++)
                        mma16816(acc[mt][nt], aa, &bb[nt][ks * 2]);
                }
            }
        }
    }
    __syncthreads();

    // ---- epilogue: work-split — gp==0 computes row rw, gp==1 row rw+8 ----
    int q = lane & 3;
    int gp = q & 1;
    int jsel = q >> 1;
    float* hsm = (float*)smem;

    float rv[4];
#pragma unroll
    for (int mt = 0; mt < 4; mt++) {
        int rw = wm * 64 + mt * 16 + (lane >> 2) + (gp ? 8 : 0);
        rv[mt] = __ldg(&rp[row0 + rw]);
    }

#pragma unroll
    for (int nt = 0; nt < 8; nt++) {
        int jl = wn * 16 + nt * 2 + jsel;
        int j  = j0 + jl;
        float vbi = svb[jl];
        float vbf = svb[32 + jl];
        float vbg = svb[64 + jl];
        float vbo = svb[96 + jl];
        float w5i = __ldg(&w576[j]);
        float w5f = __ldg(&w576[HDIM + j]);
        float w5g = __ldg(&w576[2 * HDIM + j]);
        float w5o = __ldg(&w576[3 * HDIM + j]);
        float cj  = __ldg(&cvec[j]);
#pragma unroll
        for (int mt = 0; mt < 4; mt++) {
            float v0 = acc[mt][nt][0], v1 = acc[mt][nt][1];
            float v2 = acc[mt][nt][2], v3 = acc[mt][nt][3];
            float p0 = __shfl_xor_sync(0xFFFFFFFFu, v0, 1);
            float p1 = __shfl_xor_sync(0xFFFFFFFFu, v1, 1);
            float p2 = __shfl_xor_sync(0xFFFFFFFFu, v2, 1);
            float p3 = __shfl_xor_sync(0xFFFFFFFFu, v3, 1);
            float zi = gp ? p2 : v0;
            float zf = gp ? p3 : v1;
            float zg = gp ? v2 : p0;
            float zo = gp ? v3 : p1;

            float r = rv[mt];
            zi += vbi + r * w5i;
            zf += vbf + r * w5f;
            zg += vbg + r * w5g;
            zo += vbo + r * w5o;

            float cn = fsig(zf) * cj + fsig(zi) * ftanh(zg);
            float hv = fsig(zo) * ftanh(cn);

            int rw = wm * 64 + mt * 16 + (lane >> 2) + (gp ? 8 : 0);
            hsm[rw * 33 + jl] = hv;
        }
    }
    __syncthreads();

#pragma unroll
    for (int i = 0; i < 16; i++) {
        int slot = tid + i * 128;
        int rw = slot >> 4, c2 = (slot & 15) * 2;
        __half2 hv = __floats2half2_rn(hsm[rw * 33 + c2], hsm[rw * 33 + c2 + 1]);
        *(__half2*)(g_hf + (size_t)(row0 + rw) * HDIM + j0 + c2) = hv;
    }
}

// ---------------------------------------------------------------------------
// heads_mma: logits = h @ Wa via HMMA; softmax; value SIMT over fp16 h.
// ---------------------------------------------------------------------------
#define H_STA 0
#define H_STB 4096
#define H_STRIDE 12288
#define H_NCH 32
#define H_SMEM (3 * H_STRIDE + 8192)
#define H_WV_OFF (3 * H_STRIDE)

__global__ __launch_bounds__(256, 2) void heads_mma(const float* __restrict__ Wv,
                                                    const float* __restrict__ ba,
                                                    const float* __restrict__ bv,
                                                    float* __restrict__ out) {
    extern __shared__ char smem[];
    uint32_t sb = smem_u32(smem);
    int tid  = threadIdx.x;
    int lane = tid & 31, w = tid >> 5;
    int wm = w & 1, wn = w >> 1;
    int row0 = blockIdx.x * 32;

    int lr = lane & 7, ls = lane >> 3;
    uint32_t a_row = wm * 16 + lr + (ls & 1) * 8;
    uint32_t a_chs = (uint32_t)(ls >> 1);
    uint32_t b_row = wn * 16 + lr;
    uint32_t b_chs = (uint32_t)(ls & 1);

    uint32_t pa0 = H_STA + (((a_row * 128) | ((a_row * 16) & 0x70)) ^ (a_chs << 4));
    uint32_t pb0 = H_STB + (((b_row * 128) | ((b_row * 16) & 0x70)) ^ (b_chs << 4));

    uint32_t sw0 = SWZ128((uint32_t)((tid >> 3) * 128 + (tid & 7) * 16));
    const __half* ph = g_hf + (size_t)(row0 + (tid >> 3)) * HDIM + (tid & 7) * 8;
    const __half* pa = g_wa + (size_t)(tid >> 3) * HDIM + (tid & 7) * 8;

    float acc[2][4];
#pragma unroll
    for (int nt = 0; nt < 2; nt++)
#pragma unroll
        for (int i = 0; i < 4; i++) acc[nt][i] = 0.0f;

#pragma unroll
    for (int st = 0; st < 2; st++) {
        uint32_t base = sb + st * H_STRIDE;
        cpa16(base + H_STA + sw0, ph + st * 64);
#pragma unroll
        for (int i = 0; i < 2; i++)
            cpa16(base + H_STB + sw0 + i * 4096, pa + (size_t)i * 32 * HDIM + st * 64);
        CPA_COMMIT();
    }

    for (int t = 0; t < H_NCH; t++) {
        if (t == H_NCH - 1) { CPA_WAIT(0); } else { CPA_WAIT(1); }
        __syncthreads();

        if (t + 2 < H_NCH) {
            uint32_t base = sb + ((t + 2) % 3) * H_STRIDE;
            int kg = (t + 2) * 64;
            cpa16(base + H_STA + sw0, ph + kg);
#pragma unroll
            for (int i = 0; i < 2; i++)
                cpa16(base + H_STB + sw0 + i * 4096, pa + (size_t)i * 32 * HDIM + kg);
            CPA_COMMIT();
        }

        uint32_t sa = sb + (t % 3) * H_STRIDE;
#pragma unroll
        for (int kb = 0; kb < 8; kb += 2) {
            uint32_t koff = (uint32_t)(kb << 4);
            uint32_t aa[4];
            ldmx4(aa, sa + (pa0 ^ koff));
#pragma unroll
            for (int nt = 0; nt < 2; nt++) {
                uint32_t bb[2];
                ldmx2(bb, sa + ((pb0 + nt * 1024) ^ koff));
                mma16816(acc[nt], aa, bb);
            }
        }
    }
    __syncthreads();

    float* lsm = (float*)smem;
    float* wvs = (float*)(smem + H_WV_OFF);
    {
        int r = wm * 16 + (lane >> 2);
#pragma unroll
        for (int nt = 0; nt < 2; nt++) {
            int c = wn * 16 + nt * 8 + (lane & 3) * 2;
            lsm[r * 65 + c]           = acc[nt][0];
            lsm[r * 65 + c + 1]       = acc[nt][1];
            lsm[(r + 8) * 65 + c]     = acc[nt][2];
            lsm[(r + 8) * 65 + c + 1] = acc[nt][3];
        }
    }
#pragma unroll
    for (int i = 0; i < 2; i++) {
        int e = tid + i * 256;
        *(float4*)&wvs[e * 4] = *(const float4*)&Wv[e * 4];
    }
    __syncthreads();

    int rowt = tid >> 3, ag = tid & 7;
    float l[8];
    float m = -INFINITY;
#pragma unroll
    for (int a = 0; a < 8; a++) {
        l[a] = lsm[rowt * 65 + ag * 8 + a] + __ldg(&ba[ag * 8 + a]);
        m = fmaxf(m, l[a]);
    }
#pragma unroll
    for (int off = 4; off > 0; off >>= 1)
        m = fmaxf(m, __shfl_xor_sync(0xFFFFFFFFu, m, off, 8));
    float sum = 0.0f;
#pragma unroll
    for (int a = 0; a < 8; a++) {
        l[a] = __expf(l[a] - m);
        sum += l[a];
    }
#pragma unroll
    for (int off = 4; off > 0; off >>= 1)
        sum += __shfl_xor_sync(0xFFFFFFFFu, sum, off, 8);
    float inv = __fdividef(1.0f, sum);
    int row = row0 + rowt;
#pragma unroll
    for (int a = 0; a < 8; a++)
        out[(size_t)row * 64 + ag * 8 + a] = l[a] * inv;

    float vacc = 0.0f;
    const __half* hrow = g_hf + (size_t)row * HDIM + ag * 256;
#pragma unroll 4
    for (int u = 0; u < 32; u++) {
        uint4 hv = *(const uint4*)(hrow + u * 8);
        __half2* h2 = (__half2*)&hv;
        int kb = ag * 256 + u * 8;
#pragma unroll
        for (int p = 0; p < 4; p++) {
            float2 f = __half22float2(h2[p]);
            vacc += f.x * wvs[kb + p * 2];
            vacc += f.y * wvs[kb + p * 2 + 1];
        }
    }
#pragma unroll
    for (int off = 4; off > 0; off >>= 1)
        vacc += __shfl_xor_sync(0xFFFFFFFFu, vacc, off, 8);
    if (ag == 0)
        out[(size_t)BATCH * 64 + row] = vacc + __ldg(&bv[0]);
}

// ---------------------------------------------------------------------------
extern "C" void kernel_launch(void* const* d_in, const int* in_sizes, int n_in,
                              void* d_out, int out_size) {
    const float* s      = (const float*)d_in[0];
    const float* a_prev = (const float*)d_in[1];
    const float* r_prev = (const float*)d_in[2];
    const float* h      = (const float*)d_in[3];
    const float* c      = (const float*)d_in[4];
    const float* Wx     = (const float*)d_in[5];
    const float* Wh     = (const float*)d_in[6];
    const float* bh     = (const float*)d_in[7];
    const float* Wa     = (const float*)d_in[8];
    const float* ba     = (const float*)d_in[9];
    const float* Wv     = (const float*)d_in[10];
    const float* bv     = (const float*)d_in[11];
    float* out = (float*)d_out;

    static bool attr_set = false;
    if (!attr_set) {
        cudaFuncSetAttribute(lstm_mma, cudaFuncAttributeMaxDynamicSharedMemorySize, SMEM_SZ);
        cudaFuncSetAttribute(heads_mma, cudaFuncAttributeMaxDynamicSharedMemorySize, H_SMEM);
        attr_set = true;
    }

    prep<<<PREP_BLOCKS, 256>>>(s, a_prev, h, Wh, Wx, Wa);
    lstm_mma<<<dim3(HDIM / 32, BATCH / 128), 128, SMEM_SZ>>>(
        c, r_prev, Wx + (size_t)(KDIM - 1) * FOURH, bh);
    heads_mma<<<BATCH / 32, 256, H_SMEM>>>(Wv, ba, bv, out);
}

// round 14
// speedup vs baseline: 1.0114x; 1.0114x over previous
#include <cuda_runtime.h>
#include <cuda_fp16.h>
#include <math.h>
#include <cstdint>

#define BATCH 4096
#define SDIM  512
#define ADIM  64
#define HDIM  2048
#define KDIM  577
#define KP    576           // s(512) + a(64); reward column folded rank-1 in epilogue
#define NCH   9
#define FOURH 8192
#define VB_CH 64

// ---------------- scratch (static device globals) ----------------
__device__ __half g_x[BATCH * KP];      // fp16 packed [s|a]
__device__ __half g_w[FOURH * KP];      // gate-interleaved rows n' = j*4 + g, K-major
__device__ __half g_wa[64 * HDIM];      // Wa transposed [n][k] K-major fp16
__device__ float g_vbp[VB_CH * FOURH];  // k-split partials of h @ Wh
__device__ __half g_hf[BATCH * HDIM];   // h_new in fp16

__device__ __forceinline__ uint32_t smem_u32(const void* p) {
    uint32_t a;
    asm("{ .reg .u64 t; cvta.to.shared.u64 t, %1; cvt.u32.u64 %0, t; }" : "=r"(a) : "l"(p));
    return a;
}
#define SWZ128(off) ((off) ^ (((off) >> 3) & 0x70))

__device__ __forceinline__ void cpa16(uint32_t smem, const void* g) {
    asm volatile("cp.async.cg.shared.global [%0], [%1], 16;" :: "r"(smem), "l"(g));
}
#define CPA_COMMIT()  asm volatile("cp.async.commit_group;" ::: "memory")
#define CPA_WAIT(n)   asm volatile("cp.async.wait_group %0;" :: "n"(n) : "memory")

__device__ __forceinline__ void ldmx4(uint32_t* r, uint32_t addr) {
    asm volatile("ldmatrix.sync.aligned.m8n8.x4.shared.b16 {%0,%1,%2,%3}, [%4];"
                 : "=r"(r[0]), "=r"(r[1]), "=r"(r[2]), "=r"(r[3]) : "r"(addr));
}
__device__ __forceinline__ void ldmx2(uint32_t* r, uint32_t addr) {
    asm volatile("ldmatrix.sync.aligned.m8n8.x2.shared.b16 {%0,%1}, [%2];"
                 : "=r"(r[0]), "=r"(r[1]) : "r"(addr));
}
__device__ __forceinline__ void mma16816(float* c, const uint32_t* a, const uint32_t* b) {
    asm volatile(
        "mma.sync.aligned.m16n8k16.row.col.f32.f16.f16.f32 "
        "{%0,%1,%2,%3}, {%4,%5,%6,%7}, {%8,%9}, {%0,%1,%2,%3};"
        : "+f"(c[0]), "+f"(c[1]), "+f"(c[2]), "+f"(c[3])
        : "r"(a[0]), "r"(a[1]), "r"(a[2]), "r"(a[3]), "r"(b[0]), "r"(b[1]));
}

// fast gate math
__device__ __forceinline__ float fsig(float x) {
    return __fdividef(1.0f, 1.0f + __expf(-x));
}
__device__ __forceinline__ float ftanh(float x) {
    return 1.0f - __fdividef(2.0f, __expf(2.0f * x) + 1.0f);
}

// ---------------------------------------------------------------------------
// prep: fused vb_partial + convW + convA + convX, DRAM/L2 roles interleaved.
//   bid < 4096:         even -> vb_partial[bid>>1] (2048), odd -> convW[bid>>1] (2048)
//   [4096, 4352)        convW[2048 .. 2304)
//   [4352, 4384)        convA (32)
//   [4384, 5536)        convX (1152)
// ---------------------------------------------------------------------------
#define PREP_BLOCKS 5536

__global__ __launch_bounds__(256) void prep(const float* __restrict__ s,
                                            const float* __restrict__ a,
                                            const float* __restrict__ h,
                                            const float* __restrict__ Wh,
                                            const float* __restrict__ Wx,
                                            const float* __restrict__ Wa) {
    __shared__ float t[64][65];
    int bid = blockIdx.x;
    int tid = threadIdx.x;

    int vb_id = -1, cw_id = -1;
    if (bid < 4096) {
        if ((bid & 1) == 0) vb_id = bid >> 1;
        else                cw_id = bid >> 1;
    } else if (bid < 4352) {
        cw_id = 2048 + (bid - 4096);
    }

    if (vb_id >= 0) {
        // ---- vb_partial: 32-row k-chunks ----
        int j  = (vb_id & 31) * 256 + tid;
        int k0 = (vb_id >> 5) * 32;
        float acc = 0.0f;
#pragma unroll 16
        for (int k = 0; k < 32; k++)
            acc += h[k0 + k] * __ldg(&Wh[(size_t)(k0 + k) * FOURH + j]);
        g_vbp[(vb_id >> 5) * FOURH + j] = acc;
    } else if (cw_id >= 0) {
        // ---- convW ----
        int n0 = (cw_id & 255) * 32;
        int k0 = (cw_id >> 8) * 64;
        int tx = tid & 31, ty = tid >> 5;
#pragma unroll
        for (int i = 0; i < 8; i++) {
            int kl = ty * 8 + i;
            t[kl][tx] = Wx[(size_t)(k0 + kl) * FOURH + n0 + tx];
        }
        __syncthreads();
        int nl = tid >> 3;
        int ch = tid & 7;
        int n  = n0 + nl;
        size_t np = (size_t)(n & 2047) * 4 + (n >> 11);
        uint4 vh;
        __half* ph = (__half*)&vh;
#pragma unroll
        for (int u = 0; u < 8; u++)
            ph[u] = __float2half_rn(t[ch * 8 + u][nl]);
        *(uint4*)&g_w[np * KP + k0 + ch * 8] = vh;
    } else if (bid < 4384) {
        // ---- convA ----
        int k0 = (bid - 4352) * 64;
#pragma unroll
        for (int i = 0; i < 16; i++) {
            int e = tid + i * 256;
            int kl = e >> 6, n = e & 63;
            t[kl][n] = Wa[(size_t)(k0 + kl) * 64 + n];
        }
        __syncthreads();
        int n = tid >> 2, kq = (tid & 3) * 16;
        uint4 v[2];
        __half* ph = (__half*)v;
#pragma unroll
        for (int u = 0; u < 16; u++)
            ph[u] = __float2half_rn(t[kq + u][n]);
        *(uint4*)&g_wa[(size_t)n * HDIM + k0 + kq]     = v[0];
        *(uint4*)&g_wa[(size_t)n * HDIM + k0 + kq + 8] = v[1];
    } else {
        // ---- convX ----
        int gid = (bid - 4384) * 256 + tid;
        int b = gid / 72, kc = gid - b * 72;
        int k0 = kc * 8;
        float4 f0, f1;
        if (k0 < SDIM) {
            f0 = *(const float4*)&s[(size_t)b * SDIM + k0];
            f1 = *(const float4*)&s[(size_t)b * SDIM + k0 + 4];
        } else {
            f0 = *(const float4*)&a[(size_t)b * ADIM + (k0 - SDIM)];
            f1 = *(const float4*)&a[(size_t)b * ADIM + (k0 - SDIM) + 4];
        }
        uint4 o;
        __half* ph = (__half*)&o;
        ph[0] = __float2half_rn(f0.x); ph[1] = __float2half_rn(f0.y);
        ph[2] = __float2half_rn(f0.z); ph[3] = __float2half_rn(f0.w);
        ph[4] = __float2half_rn(f1.x); ph[5] = __float2half_rn(f1.y);
        ph[6] = __float2half_rn(f1.z); ph[7] = __float2half_rn(f1.w);
        *(uint4*)&g_x[(size_t)b * KP + k0] = o;
    }
}

// ---------------------------------------------------------------------------
// lstm_mma: 4 warps (2x2), 64x64 per warp. (unchanged from R13 — at plateau)
// ---------------------------------------------------------------------------
#define ST_A   0
#define ST_B   16384
#define ST_STRIDE 32768
#define SVB_OFF  (3 * ST_STRIDE)
#define SMEM_SZ  (3 * ST_STRIDE + 512)

__global__ __launch_bounds__(128, 2) void lstm_mma(const float* __restrict__ cvec,
                                                   const float* __restrict__ rp,
                                                   const float* __restrict__ w576,
                                                   const float* __restrict__ bh) {
    extern __shared__ char smem[];
    uint32_t sb = smem_u32(smem);
    int tid  = threadIdx.x;
    int lane = tid & 31, w = tid >> 5;
    int wm = w & 1, wn = w >> 1;          // 2 x 2 warp grid, 64x64 tiles
    int row0 = blockIdx.y * 128;
    int j0   = blockIdx.x * 32;

    int lr = lane & 7, ls = lane >> 3;
    uint32_t a_row = wm * 64 + lr + (ls & 1) * 8;   // + mt*16
    uint32_t a_chs = (uint32_t)(ls >> 1);
    uint32_t b_row = wn * 64 + lr;                  // + nt*8

    uint32_t pa0 = ST_A + (((a_row * 128) | ((a_row * 16) & 0x70)) ^ (a_chs << 4));
    uint32_t pb0 = ST_B + (((b_row * 128) | ((b_row * 16) & 0x70)) ^ ((uint32_t)ls << 4));

    uint32_t sw0 = SWZ128((uint32_t)((tid >> 3) * 128 + (tid & 7) * 16));
    const __half* px = g_x + (size_t)(row0 + (tid >> 3)) * KP + (tid & 7) * 8;
    const __half* pw = g_w + (size_t)(j0 * 4 + (tid >> 3)) * KP + (tid & 7) * 8;

    float acc[4][8][4];
#pragma unroll
    for (int mt = 0; mt < 4; mt++)
#pragma unroll
        for (int nt = 0; nt < 8; nt++)
#pragma unroll
            for (int i = 0; i < 4; i++) acc[mt][nt][i] = 0.0f;

#pragma unroll
    for (int st = 0; st < 2; st++) {
        uint32_t base = sb + st * ST_STRIDE;
#pragma unroll
        for (int i = 0; i < 8; i++) {
            cpa16(base + ST_A + sw0 + i * 2048, px + (size_t)i * 16 * KP + st * 64);
            cpa16(base + ST_B + sw0 + i * 2048, pw + (size_t)i * 16 * KP + st * 64);
        }
        CPA_COMMIT();
    }

    float* svb = (float*)(smem + SVB_OFF);
    {
        int j = (tid >> 5) * HDIM + j0 + (tid & 31);
        float acc_vb = __ldg(&bh[j]);
#pragma unroll
        for (int kc = 0; kc < VB_CH; kc++) acc_vb += g_vbp[kc * FOURH + j];
        svb[tid] = acc_vb;
    }

    for (int t = 0; t < NCH; t++) {
        if (t == NCH - 1) { CPA_WAIT(0); } else { CPA_WAIT(1); }
        __syncthreads();

        if (t + 2 < NCH) {
            uint32_t base = sb + ((t + 2) % 3) * ST_STRIDE;
            int kg = (t + 2) * 64;
#pragma unroll
            for (int i = 0; i < 8; i++) {
                cpa16(base + ST_A + sw0 + i * 2048, px + (size_t)i * 16 * KP + kg);
                cpa16(base + ST_B + sw0 + i * 2048, pw + (size_t)i * 16 * KP + kg);
            }
            CPA_COMMIT();
        }

        uint32_t sa = sb + (t % 3) * ST_STRIDE;
        uint32_t aA[4], aB[8];
#pragma unroll
        for (int mt = 0; mt < 4; mt++) aA[mt] = sa + pa0 + mt * 2048;
#pragma unroll
        for (int nt = 0; nt < 8; nt++) aB[nt] = sa + pb0 + nt * 1024;

#pragma unroll
        for (int half = 0; half < 2; half++) {
            uint32_t hoff = (uint32_t)(half << 6);
            uint32_t bb[8][4];
#pragma unroll
            for (int nt = 0; nt < 8; nt++)
                ldmx4(bb[nt], aB[nt] ^ hoff);
#pragma unroll
            for (int ks = 0; ks < 2; ks++) {
                uint32_t koff = hoff + (uint32_t)(ks << 5);
#pragma unroll
                for (int mt = 0; mt < 4; mt++) {
                    uint32_t aa[4];
                    ldmx4(aa, aA[mt] ^ koff);
#pragma unroll
                    for (int nt = 0; nt < 8; nt++)
                        mma16816(acc[mt][nt], aa, &bb[nt][ks * 2]);
                }
            }
        }
    }
    __syncthreads();

    // ---- epilogue ----
    int q = lane & 3;
    int gp = q & 1;
    int jsel = q >> 1;
    float* hsm = (float*)smem;

    float rv[4];
#pragma unroll
    for (int mt = 0; mt < 4; mt++) {
        int rw = wm * 64 + mt * 16 + (lane >> 2) + (gp ? 8 : 0);
        rv[mt] = __ldg(&rp[row0 + rw]);
    }

#pragma unroll
    for (int nt = 0; nt < 8; nt++) {
        int jl = wn * 16 + nt * 2 + jsel;
        int j  = j0 + jl;
        float vbi = svb[jl];
        float vbf = svb[32 + jl];
        float vbg = svb[64 + jl];
        float vbo = svb[96 + jl];
        float w5i = __ldg(&w576[j]);
        float w5f = __ldg(&w576[HDIM + j]);
        float w5g = __ldg(&w576[2 * HDIM + j]);
        float w5o = __ldg(&w576[3 * HDIM + j]);
        float cj  = __ldg(&cvec[j]);
#pragma unroll
        for (int mt = 0; mt < 4; mt++) {
            float v0 = acc[mt][nt][0], v1 = acc[mt][nt][1];
            float v2 = acc[mt][nt][2], v3 = acc[mt][nt][3];
            float p0 = __shfl_xor_sync(0xFFFFFFFFu, v0, 1);
            float p1 = __shfl_xor_sync(0xFFFFFFFFu, v1, 1);
            float p2 = __shfl_xor_sync(0xFFFFFFFFu, v2, 1);
            float p3 = __shfl_xor_sync(0xFFFFFFFFu, v3, 1);
            float zi = gp ? p2 : v0;
            float zf = gp ? p3 : v1;
            float zg = gp ? v2 : p0;
            float zo = gp ? v3 : p1;

            float r = rv[mt];
            zi += vbi + r * w5i;
            zf += vbf + r * w5f;
            zg += vbg + r * w5g;
            zo += vbo + r * w5o;

            float cn = fsig(zf) * cj + fsig(zi) * ftanh(zg);
            float hv = fsig(zo) * ftanh(cn);

            int rw = wm * 64 + mt * 16 + (lane >> 2) + (gp ? 8 : 0);
            hsm[rw * 33 + jl] = hv;
        }
    }
    __syncthreads();

#pragma unroll
    for (int i = 0; i < 16; i++) {
        int slot = tid + i * 128;
        int rw = slot >> 4, c2 = (slot & 15) * 2;
        __half2 hv = __floats2half2_rn(hsm[rw * 33 + c2], hsm[rw * 33 + c2 + 1]);
        *(__half2*)(g_hf + (size_t)(row0 + rw) * HDIM + j0 + c2) = hv;
    }
}

// ---------------------------------------------------------------------------
// heads_mma: 16 rows/block (grid 256 — fills the chip), 8 warps x (m16 n8).
// ---------------------------------------------------------------------------
#define H_STA 0
#define H_STB 2048
#define H_STRIDE 10240
#define H_NCH 32
#define H_WV_OFF (3 * H_STRIDE)
#define H_SMEM (3 * H_STRIDE + 8192)

__global__ __launch_bounds__(256, 2) void heads_mma(const float* __restrict__ Wv,
                                                    const float* __restrict__ ba,
                                                    const float* __restrict__ bv,
                                                    float* __restrict__ out) {
    extern __shared__ char smem[];
    uint32_t sb = smem_u32(smem);
    int tid  = threadIdx.x;
    int lane = tid & 31, w = tid >> 5;   // 8 warps, warp w -> action cols [w*8, w*8+8)
    int row0 = blockIdx.x * 16;

    int lr = lane & 7, ls = lane >> 3;
    uint32_t a_row = lr + (ls & 1) * 8;            // 0..15
    uint32_t a_chs = (uint32_t)(ls >> 1);
    uint32_t b_row = w * 8 + lr;                   // 0..63
    uint32_t b_chs = (uint32_t)(ls & 1);

    uint32_t pa0 = H_STA + (((a_row * 128) | ((a_row * 16) & 0x70)) ^ (a_chs << 4));
    uint32_t pb0 = H_STB + (((b_row * 128) | ((b_row * 16) & 0x70)) ^ (b_chs << 4));

    // cp.async: threads 0-127 load A (16 rows x 8 chunks); all load 2 B slots
    uint32_t swA = SWZ128((uint32_t)((tid >> 3) * 128 + (tid & 7) * 16));
    const __half* ph = g_hf + (size_t)(row0 + (tid >> 3)) * HDIM + (tid & 7) * 8;
    const __half* pa = g_wa + (size_t)(tid >> 3) * HDIM + (tid & 7) * 8;

    float acc[4] = {0.f, 0.f, 0.f, 0.f};

#pragma unroll
    for (int st = 0; st < 2; st++) {
        uint32_t base = sb + st * H_STRIDE;
        if (tid < 128)
            cpa16(base + H_STA + swA, ph + st * 64);
#pragma unroll
        for (int i = 0; i < 2; i++) {
            int slot = tid + i * 256;
            uint32_t sw = SWZ128((uint32_t)((slot >> 3) * 128 + (slot & 7) * 16));
            cpa16(base + H_STB + sw, g_wa + (size_t)(slot >> 3) * HDIM + (slot & 7) * 8 + st * 64);
        }
        CPA_COMMIT();
    }

    for (int t = 0; t < H_NCH; t++) {
        if (t == H_NCH - 1) { CPA_WAIT(0); } else { CPA_WAIT(1); }
        __syncthreads();

        if (t + 2 < H_NCH) {
            uint32_t base = sb + ((t + 2) % 3) * H_STRIDE;
            int kg = (t + 2) * 64;
            if (tid < 128)
                cpa16(base + H_STA + swA, ph + kg);
#pragma unroll
            for (int i = 0; i < 2; i++) {
                int slot = tid + i * 256;
                uint32_t sw = SWZ128((uint32_t)((slot >> 3) * 128 + (slot & 7) * 16));
                cpa16(base + H_STB + sw, g_wa + (size_t)(slot >> 3) * HDIM + (slot & 7) * 8 + kg);
            }
            CPA_COMMIT();
        }

        uint32_t sa = sb + (t % 3) * H_STRIDE;
#pragma unroll
        for (int kb = 0; kb < 8; kb += 2) {
            uint32_t koff = (uint32_t)(kb << 4);
            uint32_t aa[4];
            ldmx4(aa, sa + (pa0 ^ koff));
            uint32_t bb[2];
            ldmx2(bb, sa + (pb0 ^ koff));
            mma16816(acc, aa, bb);
        }
    }
    __syncthreads();

    // stage logits [16][65] + Wv to smem
    float* lsm = (float*)smem;
    float* wvs = (float*)(smem + H_WV_OFF);
    {
        int r = lane >> 2;
        int c = w * 8 + (lane & 3) * 2;
        lsm[r * 65 + c]           = acc[0];
        lsm[r * 65 + c + 1]       = acc[1];
        lsm[(r + 8) * 65 + c]     = acc[2];
        lsm[(r + 8) * 65 + c + 1] = acc[3];
    }
#pragma unroll
    for (int i = 0; i < 2; i++) {
        int e = tid + i * 256;
        *(float4*)&wvs[e * 4] = *(const float4*)&Wv[e * 4];
    }
    __syncthreads();

    // softmax: 16 rows x 16 lanes; each lane owns 4 actions
    int rowt = tid >> 4, ag = tid & 15;
    float l[4];
    float m = -INFINITY;
#pragma unroll
    for (int a = 0; a < 4; a++) {
        l[a] = lsm[rowt * 65 + ag * 4 + a] + __ldg(&ba[ag * 4 + a]);
        m = fmaxf(m, l[a]);
    }
#pragma unroll
    for (int off = 8; off > 0; off >>= 1)
        m = fmaxf(m, __shfl_xor_sync(0xFFFFFFFFu, m, off, 16));
    float sum = 0.0f;
#pragma unroll
    for (int a = 0; a < 4; a++) {
        l[a] = __expf(l[a] - m);
        sum += l[a];
    }
#pragma unroll
    for (int off = 8; off > 0; off >>= 1)
        sum += __shfl_xor_sync(0xFFFFFFFFu, sum, off, 16);
    float inv = __fdividef(1.0f, sum);
    int row = row0 + rowt;
#pragma unroll
    for (int a = 0; a < 4; a++)
        out[(size_t)row * 64 + ag * 4 + a] = l[a] * inv;

    // value: 16 lanes x 128 K each
    float vacc = 0.0f;
    const __half* hrow = g_hf + (size_t)row * HDIM + ag * 128;
#pragma unroll 4
    for (int u = 0; u < 16; u++) {
        uint4 hv = *(const uint4*)(hrow + u * 8);
        __half2* h2 = (__half2*)&hv;
        int kb = ag * 128 + u * 8;
#pragma unroll
        for (int p = 0; p < 4; p++) {
            float2 f = __half22float2(h2[p]);
            vacc += f.x * wvs[kb + p * 2];
            vacc += f.y * wvs[kb + p * 2 + 1];
        }
    }
#pragma unroll
    for (int off = 8; off > 0; off >>= 1)
        vacc += __shfl_xor_sync(0xFFFFFFFFu, vacc, off, 16);
    if (ag == 0)
        out[(size_t)BATCH * 64 + row] = vacc + __ldg(&bv[0]);
}

// ---------------------------------------------------------------------------
extern "C" void kernel_launch(void* const* d_in, const int* in_sizes, int n_in,
                              void* d_out, int out_size) {
    const float* s      = (const float*)d_in[0];
    const float* a_prev = (const float*)d_in[1];
    const float* r_prev = (const float*)d_in[2];
    const float* h      = (const float*)d_in[3];
    const float* c      = (const float*)d_in[4];
    const float* Wx     = (const float*)d_in[5];
    const float* Wh     = (const float*)d_in[6];
    const float* bh     = (const float*)d_in[7];
    const float* Wa     = (const float*)d_in[8];
    const float* ba     = (const float*)d_in[9];
    const float* Wv     = (const float*)d_in[10];
    const float* bv     = (const float*)d_in[11];
    float* out = (float*)d_out;

    static bool attr_set = false;
    if (!attr_set) {
        cudaFuncSetAttribute(lstm_mma, cudaFuncAttributeMaxDynamicSharedMemorySize, SMEM_SZ);
        cudaFuncSetAttribute(heads_mma, cudaFuncAttributeMaxDynamicSharedMemorySize, H_SMEM);
        attr_set = true;
    }

    prep<<<PREP_BLOCKS, 256>>>(s, a_prev, h, Wh, Wx, Wa);
    lstm_mma<<<dim3(HDIM / 32, BATCH / 128), 128, SMEM_SZ>>>(
        c, r_prev, Wx + (size_t)(KDIM - 1) * FOURH, bh);
    heads_mma<<<BATCH / 16, 256, H_SMEM>>>(Wv, ba, bv, out);
}

// round 15
// speedup vs baseline: 1.0532x; 1.0413x over previous
#include <cuda_runtime.h>
#include <cuda_fp16.h>
#include <math.h>
#include <cstdint>

#define BATCH 4096
#define SDIM  512
#define ADIM  64
#define HDIM  2048
#define KDIM  577
#define KP    576           // s(512) + a(64); reward column folded rank-1 in epilogue
#define NCH   9
#define FOURH 8192
#define VB_CH 64

// ---------------- scratch (static device globals) ----------------
__device__ __half g_x[BATCH * KP];      // fp16 packed [s|a]
__device__ __half g_w[FOURH * KP];      // gate-interleaved rows n' = j*4 + g, K-major
__device__ __half g_wa[64 * HDIM];      // Wa transposed [n][k] K-major fp16
__device__ float g_vbp[VB_CH * FOURH];  // k-split partials of h @ Wh
__device__ __half g_hf[BATCH * HDIM];   // h_new in fp16

__device__ __forceinline__ uint32_t smem_u32(const void* p) {
    uint32_t a;
    asm("{ .reg .u64 t; cvta.to.shared.u64 t, %1; cvt.u32.u64 %0, t; }" : "=r"(a) : "l"(p));
    return a;
}
#define SWZ128(off) ((off) ^ (((off) >> 3) & 0x70))

__device__ __forceinline__ void cpa16(uint32_t smem, const void* g) {
    asm volatile("cp.async.cg.shared.global [%0], [%1], 16;" :: "r"(smem), "l"(g));
}
#define CPA_COMMIT()  asm volatile("cp.async.commit_group;" ::: "memory")
#define CPA_WAIT(n)   asm volatile("cp.async.wait_group %0;" :: "n"(n) : "memory")

__device__ __forceinline__ void ldmx4(uint32_t* r, uint32_t addr) {
    asm volatile("ldmatrix.sync.aligned.m8n8.x4.shared.b16 {%0,%1,%2,%3}, [%4];"
                 : "=r"(r[0]), "=r"(r[1]), "=r"(r[2]), "=r"(r[3]) : "r"(addr));
}
__device__ __forceinline__ void ldmx2(uint32_t* r, uint32_t addr) {
    asm volatile("ldmatrix.sync.aligned.m8n8.x2.shared.b16 {%0,%1}, [%2];"
                 : "=r"(r[0]), "=r"(r[1]) : "r"(addr));
}
__device__ __forceinline__ void mma16816(float* c, const uint32_t* a, const uint32_t* b) {
    asm volatile(
        "mma.sync.aligned.m16n8k16.row.col.f32.f16.f16.f32 "
        "{%0,%1,%2,%3}, {%4,%5,%6,%7}, {%8,%9}, {%0,%1,%2,%3};"
        : "+f"(c[0]), "+f"(c[1]), "+f"(c[2]), "+f"(c[3])
        : "r"(a[0]), "r"(a[1]), "r"(a[2]), "r"(a[3]), "r"(b[0]), "r"(b[1]));
}

// fast gate math
__device__ __forceinline__ float fsig(float x) {
    return __fdividef(1.0f, 1.0f + __expf(-x));
}
__device__ __forceinline__ float ftanh(float x) {
    return 1.0f - __fdividef(2.0f, __expf(2.0f * x) + 1.0f);
}

// ---------------------------------------------------------------------------
// prep: fused vb_partial + convW + convA + convX, DRAM/L2 roles interleaved.
// ---------------------------------------------------------------------------
#define PREP_BLOCKS 5536

__global__ __launch_bounds__(256) void prep(const float* __restrict__ s,
                                            const float* __restrict__ a,
                                            const float* __restrict__ h,
                                            const float* __restrict__ Wh,
                                            const float* __restrict__ Wx,
                                            const float* __restrict__ Wa) {
    __shared__ float t[64][65];
    int bid = blockIdx.x;
    int tid = threadIdx.x;

    int vb_id = -1, cw_id = -1;
    if (bid < 4096) {
        if ((bid & 1) == 0) vb_id = bid >> 1;
        else                cw_id = bid >> 1;
    } else if (bid < 4352) {
        cw_id = 2048 + (bid - 4096);
    }

    if (vb_id >= 0) {
        int j  = (vb_id & 31) * 256 + tid;
        int k0 = (vb_id >> 5) * 32;
        float acc = 0.0f;
#pragma unroll 16
        for (int k = 0; k < 32; k++)
            acc += h[k0 + k] * __ldg(&Wh[(size_t)(k0 + k) * FOURH + j]);
        g_vbp[(vb_id >> 5) * FOURH + j] = acc;
    } else if (cw_id >= 0) {
        int n0 = (cw_id & 255) * 32;
        int k0 = (cw_id >> 8) * 64;
        int tx = tid & 31, ty = tid >> 5;
#pragma unroll
        for (int i = 0; i < 8; i++) {
            int kl = ty * 8 + i;
            t[kl][tx] = Wx[(size_t)(k0 + kl) * FOURH + n0 + tx];
        }
        __syncthreads();
        int nl = tid >> 3;
        int ch = tid & 7;
        int n  = n0 + nl;
        size_t np = (size_t)(n & 2047) * 4 + (n >> 11);
        uint4 vh;
        __half* ph = (__half*)&vh;
#pragma unroll
        for (int u = 0; u < 8; u++)
            ph[u] = __float2half_rn(t[ch * 8 + u][nl]);
        *(uint4*)&g_w[np * KP + k0 + ch * 8] = vh;
    } else if (bid < 4384) {
        int k0 = (bid - 4352) * 64;
#pragma unroll
        for (int i = 0; i < 16; i++) {
            int e = tid + i * 256;
            int kl = e >> 6, n = e & 63;
            t[kl][n] = Wa[(size_t)(k0 + kl) * 64 + n];
        }
        __syncthreads();
        int n = tid >> 2, kq = (tid & 3) * 16;
        uint4 v[2];
        __half* ph = (__half*)v;
#pragma unroll
        for (int u = 0; u < 16; u++)
            ph[u] = __float2half_rn(t[kq + u][n]);
        *(uint4*)&g_wa[(size_t)n * HDIM + k0 + kq]     = v[0];
        *(uint4*)&g_wa[(size_t)n * HDIM + k0 + kq + 8] = v[1];
    } else {
        int gid = (bid - 4384) * 256 + tid;
        int b = gid / 72, kc = gid - b * 72;
        int k0 = kc * 8;
        float4 f0, f1;
        if (k0 < SDIM) {
            f0 = *(const float4*)&s[(size_t)b * SDIM + k0];
            f1 = *(const float4*)&s[(size_t)b * SDIM + k0 + 4];
        } else {
            f0 = *(const float4*)&a[(size_t)b * ADIM + (k0 - SDIM)];
            f1 = *(const float4*)&a[(size_t)b * ADIM + (k0 - SDIM) + 4];
        }
        uint4 o;
        __half* ph = (__half*)&o;
        ph[0] = __float2half_rn(f0.x); ph[1] = __float2half_rn(f0.y);
        ph[2] = __float2half_rn(f0.z); ph[3] = __float2half_rn(f0.w);
        ph[4] = __float2half_rn(f1.x); ph[5] = __float2half_rn(f1.y);
        ph[6] = __float2half_rn(f1.z); ph[7] = __float2half_rn(f1.w);
        *(uint4*)&g_x[(size_t)b * KP + k0] = o;
    }
}

// ---------------------------------------------------------------------------
// lstm_mma: 4 warps (2x2), 64x64 per warp. Mid-chunk prefetch; epilogue
// operands staged to smem during prologue.
// smem: 3 x 32KB pipe | [SVB_OFF] vb(128) w576(128) cvec(32) rp(128) floats
// ---------------------------------------------------------------------------
#define ST_A   0
#define ST_B   16384
#define ST_STRIDE 32768
#define SVB_OFF  (3 * ST_STRIDE)
#define SMEM_SZ  (3 * ST_STRIDE + 2048)

__global__ __launch_bounds__(128, 2) void lstm_mma(const float* __restrict__ cvec,
                                                   const float* __restrict__ rp,
                                                   const float* __restrict__ w576,
                                                   const float* __restrict__ bh) {
    extern __shared__ char smem[];
    uint32_t sb = smem_u32(smem);
    int tid  = threadIdx.x;
    int lane = tid & 31, w = tid >> 5;
    int wm = w & 1, wn = w >> 1;          // 2 x 2 warp grid, 64x64 tiles
    int row0 = blockIdx.y * 128;
    int j0   = blockIdx.x * 32;

    int lr = lane & 7, ls = lane >> 3;
    uint32_t a_row = wm * 64 + lr + (ls & 1) * 8;   // + mt*16
    uint32_t a_chs = (uint32_t)(ls >> 1);
    uint32_t b_row = wn * 64 + lr;                  // + nt*8

    uint32_t pa0 = ST_A + (((a_row * 128) | ((a_row * 16) & 0x70)) ^ (a_chs << 4));
    uint32_t pb0 = ST_B + (((b_row * 128) | ((b_row * 16) & 0x70)) ^ ((uint32_t)ls << 4));

    uint32_t sw0 = SWZ128((uint32_t)((tid >> 3) * 128 + (tid & 7) * 16));
    const __half* px = g_x + (size_t)(row0 + (tid >> 3)) * KP + (tid & 7) * 8;
    const __half* pw = g_w + (size_t)(j0 * 4 + (tid >> 3)) * KP + (tid & 7) * 8;

    float acc[4][8][4];
#pragma unroll
    for (int mt = 0; mt < 4; mt++)
#pragma unroll
        for (int nt = 0; nt < 8; nt++)
#pragma unroll
            for (int i = 0; i < 4; i++) acc[mt][nt][i] = 0.0f;

#pragma unroll
    for (int st = 0; st < 2; st++) {
        uint32_t base = sb + st * ST_STRIDE;
#pragma unroll
        for (int i = 0; i < 8; i++) {
            cpa16(base + ST_A + sw0 + i * 2048, px + (size_t)i * 16 * KP + st * 64);
            cpa16(base + ST_B + sw0 + i * 2048, pw + (size_t)i * 16 * KP + st * 64);
        }
        CPA_COMMIT();
    }

    // stage epilogue operands into smem (overlaps prologue cp.async)
    float* svb = (float*)(smem + SVB_OFF);        // [0:128) vb
    float* w5s = svb + 128;                        // [128:256) w576 gate-major
    float* csm = svb + 256;                        // [256:288) cvec
    float* rsm = svb + 288;                        // [288:416) rp
    {
        int g = tid >> 5, jl = tid & 31;
        int j = g * HDIM + j0 + jl;
        float acc_vb = __ldg(&bh[j]);
#pragma unroll
        for (int kc = 0; kc < VB_CH; kc++) acc_vb += g_vbp[kc * FOURH + j];
        svb[tid] = acc_vb;
        w5s[tid] = __ldg(&w576[j]);
        rsm[tid] = __ldg(&rp[row0 + tid]);
        if (tid < 32) csm[tid] = __ldg(&cvec[j0 + tid]);
    }

    for (int t = 0; t < NCH; t++) {
        if (t == NCH - 1) { CPA_WAIT(0); } else { CPA_WAIT(1); }
        __syncthreads();

        uint32_t sa = sb + (t % 3) * ST_STRIDE;
        uint32_t aA[4], aB[8];
#pragma unroll
        for (int mt = 0; mt < 4; mt++) aA[mt] = sa + pa0 + mt * 2048;
#pragma unroll
        for (int nt = 0; nt < 8; nt++) aB[nt] = sa + pb0 + nt * 1024;

        // ---- half 0 ----
        {
            uint32_t bb[8][4];
#pragma unroll
            for (int nt = 0; nt < 8; nt++)
                ldmx4(bb[nt], aB[nt]);
#pragma unroll
            for (int ks = 0; ks < 2; ks++) {
                uint32_t koff = (uint32_t)(ks << 5);
#pragma unroll
                for (int mt = 0; mt < 4; mt++) {
                    uint32_t aa[4];
                    ldmx4(aa, aA[mt] ^ koff);
#pragma unroll
                    for (int nt = 0; nt < 8; nt++)
                        mma16816(acc[mt][nt], aa, &bb[nt][ks * 2]);
                }
            }
        }

        // mid-chunk prefetch of chunk t+2 (de-bursts MIO vs chunk-start LDSM)
        if (t + 2 < NCH) {
            uint32_t base = sb + ((t + 2) % 3) * ST_STRIDE;
            int kg = (t + 2) * 64;
#pragma unroll
            for (int i = 0; i < 8; i++) {
                cpa16(base + ST_A + sw0 + i * 2048, px + (size_t)i * 16 * KP + kg);
                cpa16(base + ST_B + sw0 + i * 2048, pw + (size_t)i * 16 * KP + kg);
            }
            CPA_COMMIT();
        }

        // ---- half 1 ----
        {
            uint32_t bb[8][4];
#pragma unroll
            for (int nt = 0; nt < 8; nt++)
                ldmx4(bb[nt], aB[nt] ^ 64u);
#pragma unroll
            for (int ks = 0; ks < 2; ks++) {
                uint32_t koff = 64u + (uint32_t)(ks << 5);
#pragma unroll
                for (int mt = 0; mt < 4; mt++) {
                    uint32_t aa[4];
                    ldmx4(aa, aA[mt] ^ koff);
#pragma unroll
                    for (int nt = 0; nt < 8; nt++)
                        mma16816(acc[mt][nt], aa, &bb[nt][ks * 2]);
                }
            }
        }
    }
    __syncthreads();

    // ---- epilogue: all operands from smem ----
    int q = lane & 3;
    int gp = q & 1;
    int jsel = q >> 1;
    float* hsm = (float*)smem;   // overlays pipe area only; svb block intact

    float rv[4];
#pragma unroll
    for (int mt = 0; mt < 4; mt++) {
        int rw = wm * 64 + mt * 16 + (lane >> 2) + (gp ? 8 : 0);
        rv[mt] = rsm[rw];
    }

#pragma unroll
    for (int nt = 0; nt < 8; nt++) {
        int jl = wn * 16 + nt * 2 + jsel;
        float vbi = svb[jl];
        float vbf = svb[32 + jl];
        float vbg = svb[64 + jl];
        float vbo = svb[96 + jl];
        float w5i = w5s[jl];
        float w5f = w5s[32 + jl];
        float w5g = w5s[64 + jl];
        float w5o = w5s[96 + jl];
        float cj  = csm[jl];
#pragma unroll
        for (int mt = 0; mt < 4; mt++) {
            float v0 = acc[mt][nt][0], v1 = acc[mt][nt][1];
            float v2 = acc[mt][nt][2], v3 = acc[mt][nt][3];
            float p0 = __shfl_xor_sync(0xFFFFFFFFu, v0, 1);
            float p1 = __shfl_xor_sync(0xFFFFFFFFu, v1, 1);
            float p2 = __shfl_xor_sync(0xFFFFFFFFu, v2, 1);
            float p3 = __shfl_xor_sync(0xFFFFFFFFu, v3, 1);
            float zi = gp ? p2 : v0;
            float zf = gp ? p3 : v1;
            float zg = gp ? v2 : p0;
            float zo = gp ? v3 : p1;

            float r = rv[mt];
            zi += vbi + r * w5i;
            zf += vbf + r * w5f;
            zg += vbg + r * w5g;
            zo += vbo + r * w5o;

            float cn = fsig(zf) * cj + fsig(zi) * ftanh(zg);
            float hv = fsig(zo) * ftanh(cn);

            int rw = wm * 64 + mt * 16 + (lane >> 2) + (gp ? 8 : 0);
            hsm[rw * 33 + jl] = hv;
        }
    }
    __syncthreads();

#pragma unroll
    for (int i = 0; i < 16; i++) {
        int slot = tid + i * 128;
        int rw = slot >> 4, c2 = (slot & 15) * 2;
        __half2 hv = __floats2half2_rn(hsm[rw * 33 + c2], hsm[rw * 33 + c2 + 1]);
        *(__half2*)(g_hf + (size_t)(row0 + rw) * HDIM + j0 + c2) = hv;
    }
}

// ---------------------------------------------------------------------------
// heads_mma: 16 rows/block (grid 256), 8 warps x (m16 n8).
// ---------------------------------------------------------------------------
#define H_STA 0
#define H_STB 2048
#define H_STRIDE 10240
#define H_NCH 32
#define H_WV_OFF (3 * H_STRIDE)
#define H_SMEM (3 * H_STRIDE + 8192)

__global__ __launch_bounds__(256, 2) void heads_mma(const float* __restrict__ Wv,
                                                    const float* __restrict__ ba,
                                                    const float* __restrict__ bv,
                                                    float* __restrict__ out) {
    extern __shared__ char smem[];
    uint32_t sb = smem_u32(smem);
    int tid  = threadIdx.x;
    int lane = tid & 31, w = tid >> 5;
    int row0 = blockIdx.x * 16;

    int lr = lane & 7, ls = lane >> 3;
    uint32_t a_row = lr + (ls & 1) * 8;
    uint32_t a_chs = (uint32_t)(ls >> 1);
    uint32_t b_row = w * 8 + lr;
    uint32_t b_chs = (uint32_t)(ls & 1);

    uint32_t pa0 = H_STA + (((a_row * 128) | ((a_row * 16) & 0x70)) ^ (a_chs << 4));
    uint32_t pb0 = H_STB + (((b_row * 128) | ((b_row * 16) & 0x70)) ^ (b_chs << 4));

    uint32_t swA = SWZ128((uint32_t)((tid >> 3) * 128 + (tid & 7) * 16));
    const __half* ph = g_hf + (size_t)(row0 + (tid >> 3)) * HDIM + (tid & 7) * 8;

    float acc[4] = {0.f, 0.f, 0.f, 0.f};

#pragma unroll
    for (int st = 0; st < 2; st++) {
        uint32_t base = sb + st * H_STRIDE;
        if (tid < 128)
            cpa16(base + H_STA + swA, ph + st * 64);
#pragma unroll
        for (int i = 0; i < 2; i++) {
            int slot = tid + i * 256;
            uint32_t sw = SWZ128((uint32_t)((slot >> 3) * 128 + (slot & 7) * 16));
            cpa16(base + H_STB + sw, g_wa + (size_t)(slot >> 3) * HDIM + (slot & 7) * 8 + st * 64);
        }
        CPA_COMMIT();
    }

    for (int t = 0; t < H_NCH; t++) {
        if (t == H_NCH - 1) { CPA_WAIT(0); } else { CPA_WAIT(1); }
        __syncthreads();

        if (t + 2 < H_NCH) {
            uint32_t base = sb + ((t + 2) % 3) * H_STRIDE;
            int kg = (t + 2) * 64;
            if (tid < 128)
                cpa16(base + H_STA + swA, ph + kg);
#pragma unroll
            for (int i = 0; i < 2; i++) {
                int slot = tid + i * 256;
                uint32_t sw = SWZ128((uint32_t)((slot >> 3) * 128 + (slot & 7) * 16));
                cpa16(base + H_STB + sw, g_wa + (size_t)(slot >> 3) * HDIM + (slot & 7) * 8 + kg);
            }
            CPA_COMMIT();
        }

        uint32_t sa = sb + (t % 3) * H_STRIDE;
#pragma unroll
        for (int kb = 0; kb < 8; kb += 2) {
            uint32_t koff = (uint32_t)(kb << 4);
            uint32_t aa[4];
            ldmx4(aa, sa + (pa0 ^ koff));
            uint32_t bb[2];
            ldmx2(bb, sa + (pb0 ^ koff));
            mma16816(acc, aa, bb);
        }
    }
    __syncthreads();

    float* lsm = (float*)smem;
    float* wvs = (float*)(smem + H_WV_OFF);
    {
        int r = lane >> 2;
        int c = w * 8 + (lane & 3) * 2;
        lsm[r * 65 + c]           = acc[0];
        lsm[r * 65 + c + 1]       = acc[1];
        lsm[(r + 8) * 65 + c]     = acc[2];
        lsm[(r + 8) * 65 + c + 1] = acc[3];
    }
#pragma unroll
    for (int i = 0; i < 2; i++) {
        int e = tid + i * 256;
        *(float4*)&wvs[e * 4] = *(const float4*)&Wv[e * 4];
    }
    __syncthreads();

    int rowt = tid >> 4, ag = tid & 15;
    float l[4];
    float m = -INFINITY;
#pragma unroll
    for (int a = 0; a < 4; a++) {
        l[a] = lsm[rowt * 65 + ag * 4 + a] + __ldg(&ba[ag * 4 + a]);
        m = fmaxf(m, l[a]);
    }
#pragma unroll
    for (int off = 8; off > 0; off >>= 1)
        m = fmaxf(m, __shfl_xor_sync(0xFFFFFFFFu, m, off, 16));
    float sum = 0.0f;
#pragma unroll
    for (int a = 0; a < 4; a++) {
        l[a] = __expf(l[a] - m);
        sum += l[a];
    }
#pragma unroll
    for (int off = 8; off > 0; off >>= 1)
        sum += __shfl_xor_sync(0xFFFFFFFFu, sum, off, 16);
    float inv = __fdividef(1.0f, sum);
    int row = row0 + rowt;
#pragma unroll
    for (int a = 0; a < 4; a++)
        out[(size_t)row * 64 + ag * 4 + a] = l[a] * inv;

    float vacc = 0.0f;
    const __half* hrow = g_hf + (size_t)row * HDIM + ag * 128;
#pragma unroll 4
    for (int u = 0; u < 16; u++) {
        uint4 hv = *(const uint4*)(hrow + u * 8);
        __half2* h2 = (__half2*)&hv;
        int kb = ag * 128 + u * 8;
#pragma unroll
        for (int p = 0; p < 4; p++) {
            float2 f = __half22float2(h2[p]);
            vacc += f.x * wvs[kb + p * 2];
            vacc += f.y * wvs[kb + p * 2 + 1];
        }
    }
#pragma unroll
    for (int off = 8; off > 0; off >>= 1)
        vacc += __shfl_xor_sync(0xFFFFFFFFu, vacc, off, 16);
    if (ag == 0)
        out[(size_t)BATCH * 64 + row] = vacc + __ldg(&bv[0]);
}

// ---------------------------------------------------------------------------
extern "C" void kernel_launch(void* const* d_in, const int* in_sizes, int n_in,
                              void* d_out, int out_size) {
    const float* s      = (const float*)d_in[0];
    const float* a_prev = (const float*)d_in[1];
    const float* r_prev = (const float*)d_in[2];
    const float* h      = (const float*)d_in[3];
    const float* c      = (const float*)d_in[4];
    const float* Wx     = (const float*)d_in[5];
    const float* Wh     = (const float*)d_in[6];
    const float* bh     = (const float*)d_in[7];
    const float* Wa     = (const float*)d_in[8];
    const float* ba     = (const float*)d_in[9];
    const float* Wv     = (const float*)d_in[10];
    const float* bv     = (const float*)d_in[11];
    float* out = (float*)d_out;

    static bool attr_set = false;
    if (!attr_set) {
        cudaFuncSetAttribute(lstm_mma, cudaFuncAttributeMaxDynamicSharedMemorySize, SMEM_SZ);
        cudaFuncSetAttribute(heads_mma, cudaFuncAttributeMaxDynamicSharedMemorySize, H_SMEM);
        attr_set = true;
    }

    prep<<<PREP_BLOCKS, 256>>>(s, a_prev, h, Wh, Wx, Wa);
    lstm_mma<<<dim3(HDIM / 32, BATCH / 128), 128, SMEM_SZ>>>(
        c, r_prev, Wx + (size_t)(KDIM - 1) * FOURH, bh);
    heads_mma<<<BATCH / 16, 256, H_SMEM>>>(Wv, ba, bv, out);
}

// round 16
// speedup vs baseline: 1.0703x; 1.0162x over previous
#include <cuda_runtime.h>
#include <cuda_fp16.h>
#include <math.h>
#include <cstdint>

#define BATCH 4096
#define SDIM  512
#define ADIM  64
#define HDIM  2048
#define KDIM  577
#define KP    576           // s(512) + a(64); reward column folded rank-1 in epilogue
#define NCH   9
#define FOURH 8192
#define VB_CH 64

// ---------------- scratch (static device globals) ----------------
__device__ __half g_x[BATCH * KP];      // fp16 packed [s|a]
__device__ __half g_w[FOURH * KP];      // gate-interleaved rows n' = j*4 + g, K-major
__device__ __half g_wa[64 * HDIM];      // Wa transposed [n][k] K-major fp16
__device__ float g_vbp[VB_CH * FOURH];  // k-split partials of h @ Wh
__device__ __half g_hf[BATCH * HDIM];   // h_new in fp16

__device__ __forceinline__ uint32_t smem_u32(const void* p) {
    uint32_t a;
    asm("{ .reg .u64 t; cvta.to.shared.u64 t, %1; cvt.u32.u64 %0, t; }" : "=r"(a) : "l"(p));
    return a;
}
#define SWZ128(off) ((off) ^ (((off) >> 3) & 0x70))

__device__ __forceinline__ void cpa16(uint32_t smem, const void* g) {
    asm volatile("cp.async.cg.shared.global [%0], [%1], 16;" :: "r"(smem), "l"(g));
}
#define CPA_COMMIT()  asm volatile("cp.async.commit_group;" ::: "memory")
#define CPA_WAIT(n)   asm volatile("cp.async.wait_group %0;" :: "n"(n) : "memory")

__device__ __forceinline__ void ldmx4(uint32_t* r, uint32_t addr) {
    asm volatile("ldmatrix.sync.aligned.m8n8.x4.shared.b16 {%0,%1,%2,%3}, [%4];"
                 : "=r"(r[0]), "=r"(r[1]), "=r"(r[2]), "=r"(r[3]) : "r"(addr));
}
__device__ __forceinline__ void ldmx2(uint32_t* r, uint32_t addr) {
    asm volatile("ldmatrix.sync.aligned.m8n8.x2.shared.b16 {%0,%1}, [%2];"
                 : "=r"(r[0]), "=r"(r[1]) : "r"(addr));
}
__device__ __forceinline__ void mma16816(float* c, const uint32_t* a, const uint32_t* b) {
    asm volatile(
        "mma.sync.aligned.m16n8k16.row.col.f32.f16.f16.f32 "
        "{%0,%1,%2,%3}, {%4,%5,%6,%7}, {%8,%9}, {%0,%1,%2,%3};"
        : "+f"(c[0]), "+f"(c[1]), "+f"(c[2]), "+f"(c[3])
        : "r"(a[0]), "r"(a[1]), "r"(a[2]), "r"(a[3]), "r"(b[0]), "r"(b[1]));
}

// fast gate math
__device__ __forceinline__ float fsig(float x) {
    return __fdividef(1.0f, 1.0f + __expf(-x));
}
__device__ __forceinline__ float ftanh(float x) {
    return 1.0f - __fdividef(2.0f, __expf(2.0f * x) + 1.0f);
}

// ---------------------------------------------------------------------------
// prep: fused vb_partial(float4) + convW + convA + convX, interleaved.
//   vb: 512 blocks (8 j-blocks of 1024 x 64 k-chunks of 32), LDG.128 on Wh
//   convW: 2304, convA: 32, convX: 1152. Total 4000.
//   bid < 1024: even -> vb[bid>>1], odd -> convW[bid>>1]
//   [1024, 2816): convW[512..2304)
//   [2816, 2848): convA     [2848, 4000): convX
// ---------------------------------------------------------------------------
#define PREP_BLOCKS 4000

__global__ __launch_bounds__(256) void prep(const float* __restrict__ s,
                                            const float* __restrict__ a,
                                            const float* __restrict__ h,
                                            const float* __restrict__ Wh,
                                            const float* __restrict__ Wx,
                                            const float* __restrict__ Wa) {
    __shared__ float t[64][65];
    int bid = blockIdx.x;
    int tid = threadIdx.x;

    int vb_id = -1, cw_id = -1;
    if (bid < 1024) {
        if ((bid & 1) == 0) vb_id = bid >> 1;
        else                cw_id = bid >> 1;
    } else if (bid < 2816) {
        cw_id = 512 + (bid - 1024);
    }

    if (vb_id >= 0) {
        // ---- vb_partial: float4 over j, 32-row k-chunks ----
        int j  = (vb_id & 7) * 1024 + tid * 4;
        int k0 = (vb_id >> 3) * 32;
        float4 acc = make_float4(0.f, 0.f, 0.f, 0.f);
#pragma unroll 8
        for (int k = 0; k < 32; k++) {
            float hv = h[k0 + k];
            float4 wv = *(const float4*)&Wh[(size_t)(k0 + k) * FOURH + j];
            acc.x += hv * wv.x;
            acc.y += hv * wv.y;
            acc.z += hv * wv.z;
            acc.w += hv * wv.w;
        }
        *(float4*)&g_vbp[(size_t)(vb_id >> 3) * FOURH + j] = acc;
    } else if (cw_id >= 0) {
        // ---- convW ----
        int n0 = (cw_id & 255) * 32;
        int k0 = (cw_id >> 8) * 64;
        int tx = tid & 31, ty = tid >> 5;
#pragma unroll
        for (int i = 0; i < 8; i++) {
            int kl = ty * 8 + i;
            t[kl][tx] = Wx[(size_t)(k0 + kl) * FOURH + n0 + tx];
        }
        __syncthreads();
        int nl = tid >> 3;
        int ch = tid & 7;
        int n  = n0 + nl;
        size_t np = (size_t)(n & 2047) * 4 + (n >> 11);
        uint4 vh;
        __half* ph = (__half*)&vh;
#pragma unroll
        for (int u = 0; u < 8; u++)
            ph[u] = __float2half_rn(t[ch * 8 + u][nl]);
        *(uint4*)&g_w[np * KP + k0 + ch * 8] = vh;
    } else if (bid < 2848) {
        // ---- convA ----
        int k0 = (bid - 2816) * 64;
#pragma unroll
        for (int i = 0; i < 16; i++) {
            int e = tid + i * 256;
            int kl = e >> 6, n = e & 63;
            t[kl][n] = Wa[(size_t)(k0 + kl) * 64 + n];
        }
        __syncthreads();
        int n = tid >> 2, kq = (tid & 3) * 16;
        uint4 v[2];
        __half* ph = (__half*)v;
#pragma unroll
        for (int u = 0; u < 16; u++)
            ph[u] = __float2half_rn(t[kq + u][n]);
        *(uint4*)&g_wa[(size_t)n * HDIM + k0 + kq]     = v[0];
        *(uint4*)&g_wa[(size_t)n * HDIM + k0 + kq + 8] = v[1];
    } else {
        // ---- convX ----
        int gid = (bid - 2848) * 256 + tid;
        int b = gid / 72, kc = gid - b * 72;
        int k0 = kc * 8;
        float4 f0, f1;
        if (k0 < SDIM) {
            f0 = *(const float4*)&s[(size_t)b * SDIM + k0];
            f1 = *(const float4*)&s[(size_t)b * SDIM + k0 + 4];
        } else {
            f0 = *(const float4*)&a[(size_t)b * ADIM + (k0 - SDIM)];
            f1 = *(const float4*)&a[(size_t)b * ADIM + (k0 - SDIM) + 4];
        }
        uint4 o;
        __half* ph = (__half*)&o;
        ph[0] = __float2half_rn(f0.x); ph[1] = __float2half_rn(f0.y);
        ph[2] = __float2half_rn(f0.z); ph[3] = __float2half_rn(f0.w);
        ph[4] = __float2half_rn(f1.x); ph[5] = __float2half_rn(f1.y);
        ph[6] = __float2half_rn(f1.z); ph[7] = __float2half_rn(f1.w);
        *(uint4*)&g_x[(size_t)b * KP + k0] = o;
    }
}

// ---------------------------------------------------------------------------
// lstm_mma: 4 warps (2x2), 64x64 per warp. Mid-chunk prefetch; smem-staged
// epilogue operands; uint4 h store.
// ---------------------------------------------------------------------------
#define ST_A   0
#define ST_B   16384
#define ST_STRIDE 32768
#define SVB_OFF  (3 * ST_STRIDE)
#define SMEM_SZ  (3 * ST_STRIDE + 2048)

__global__ __launch_bounds__(128, 2) void lstm_mma(const float* __restrict__ cvec,
                                                   const float* __restrict__ rp,
                                                   const float* __restrict__ w576,
                                                   const float* __restrict__ bh) {
    extern __shared__ char smem[];
    uint32_t sb = smem_u32(smem);
    int tid  = threadIdx.x;
    int lane = tid & 31, w = tid >> 5;
    int wm = w & 1, wn = w >> 1;          // 2 x 2 warp grid, 64x64 tiles
    int row0 = blockIdx.y * 128;
    int j0   = blockIdx.x * 32;

    int lr = lane & 7, ls = lane >> 3;
    uint32_t a_row = wm * 64 + lr + (ls & 1) * 8;   // + mt*16
    uint32_t a_chs = (uint32_t)(ls >> 1);
    uint32_t b_row = wn * 64 + lr;                  // + nt*8

    uint32_t pa0 = ST_A + (((a_row * 128) | ((a_row * 16) & 0x70)) ^ (a_chs << 4));
    uint32_t pb0 = ST_B + (((b_row * 128) | ((b_row * 16) & 0x70)) ^ ((uint32_t)ls << 4));

    uint32_t sw0 = SWZ128((uint32_t)((tid >> 3) * 128 + (tid & 7) * 16));
    const __half* px = g_x + (size_t)(row0 + (tid >> 3)) * KP + (tid & 7) * 8;
    const __half* pw = g_w + (size_t)(j0 * 4 + (tid >> 3)) * KP + (tid & 7) * 8;

    float acc[4][8][4];
#pragma unroll
    for (int mt = 0; mt < 4; mt++)
#pragma unroll
        for (int nt = 0; nt < 8; nt++)
#pragma unroll
            for (int i = 0; i < 4; i++) acc[mt][nt][i] = 0.0f;

#pragma unroll
    for (int st = 0; st < 2; st++) {
        uint32_t base = sb + st * ST_STRIDE;
#pragma unroll
        for (int i = 0; i < 8; i++) {
            cpa16(base + ST_A + sw0 + i * 2048, px + (size_t)i * 16 * KP + st * 64);
            cpa16(base + ST_B + sw0 + i * 2048, pw + (size_t)i * 16 * KP + st * 64);
        }
        CPA_COMMIT();
    }

    // stage epilogue operands into smem (overlaps prologue cp.async)
    float* svb = (float*)(smem + SVB_OFF);        // [0:128) vb
    float* w5s = svb + 128;                        // [128:256) w576 gate-major
    float* csm = svb + 256;                        // [256:288) cvec
    float* rsm = svb + 288;                        // [288:416) rp
    {
        int g = tid >> 5, jl = tid & 31;
        int j = g * HDIM + j0 + jl;
        float acc_vb = __ldg(&bh[j]);
#pragma unroll
        for (int kc = 0; kc < VB_CH; kc++) acc_vb += g_vbp[kc * FOURH + j];
        svb[tid] = acc_vb;
        w5s[tid] = __ldg(&w576[j]);
        rsm[tid] = __ldg(&rp[row0 + tid]);
        if (tid < 32) csm[tid] = __ldg(&cvec[j0 + tid]);
    }

    for (int t = 0; t < NCH; t++) {
        if (t == NCH - 1) { CPA_WAIT(0); } else { CPA_WAIT(1); }
        __syncthreads();

        uint32_t sa = sb + (t % 3) * ST_STRIDE;
        uint32_t aA[4], aB[8];
#pragma unroll
        for (int mt = 0; mt < 4; mt++) aA[mt] = sa + pa0 + mt * 2048;
#pragma unroll
        for (int nt = 0; nt < 8; nt++) aB[nt] = sa + pb0 + nt * 1024;

        // ---- half 0 ----
        {
            uint32_t bb[8][4];
#pragma unroll
            for (int nt = 0; nt < 8; nt++)
                ldmx4(bb[nt], aB[nt]);
#pragma unroll
            for (int ks = 0; ks < 2; ks++) {
                uint32_t koff = (uint32_t)(ks << 5);
#pragma unroll
                for (int mt = 0; mt < 4; mt++) {
                    uint32_t aa[4];
                    ldmx4(aa, aA[mt] ^ koff);
#pragma unroll
                    for (int nt = 0; nt < 8; nt++)
                        mma16816(acc[mt][nt], aa, &bb[nt][ks * 2]);
                }
            }
        }

        // mid-chunk prefetch of chunk t+2
        if (t + 2 < NCH) {
            uint32_t base = sb + ((t + 2) % 3) * ST_STRIDE;
            int kg = (t + 2) * 64;
#pragma unroll
            for (int i = 0; i < 8; i++) {
                cpa16(base + ST_A + sw0 + i * 2048, px + (size_t)i * 16 * KP + kg);
                cpa16(base + ST_B + sw0 + i * 2048, pw + (size_t)i * 16 * KP + kg);
            }
            CPA_COMMIT();
        }

        // ---- half 1 ----
        {
            uint32_t bb[8][4];
#pragma unroll
            for (int nt = 0; nt < 8; nt++)
                ldmx4(bb[nt], aB[nt] ^ 64u);
#pragma unroll
            for (int ks = 0; ks < 2; ks++) {
                uint32_t koff = 64u + (uint32_t)(ks << 5);
#pragma unroll
                for (int mt = 0; mt < 4; mt++) {
                    uint32_t aa[4];
                    ldmx4(aa, aA[mt] ^ koff);
#pragma unroll
                    for (int nt = 0; nt < 8; nt++)
                        mma16816(acc[mt][nt], aa, &bb[nt][ks * 2]);
                }
            }
        }
    }
    __syncthreads();

    // ---- epilogue: all operands from smem ----
    int q = lane & 3;
    int gp = q & 1;
    int jsel = q >> 1;
    float* hsm = (float*)smem;   // overlays pipe area only; svb block intact

    float rv[4];
#pragma unroll
    for (int mt = 0; mt < 4; mt++) {
        int rw = wm * 64 + mt * 16 + (lane >> 2) + (gp ? 8 : 0);
        rv[mt] = rsm[rw];
    }

#pragma unroll
    for (int nt = 0; nt < 8; nt++) {
        int jl = wn * 16 + nt * 2 + jsel;
        float vbi = svb[jl];
        float vbf = svb[32 + jl];
        float vbg = svb[64 + jl];
        float vbo = svb[96 + jl];
        float w5i = w5s[jl];
        float w5f = w5s[32 + jl];
        float w5g = w5s[64 + jl];
        float w5o = w5s[96 + jl];
        float cj  = csm[jl];
#pragma unroll
        for (int mt = 0; mt < 4; mt++) {
            float v0 = acc[mt][nt][0], v1 = acc[mt][nt][1];
            float v2 = acc[mt][nt][2], v3 = acc[mt][nt][3];
            float p0 = __shfl_xor_sync(0xFFFFFFFFu, v0, 1);
            float p1 = __shfl_xor_sync(0xFFFFFFFFu, v1, 1);
            float p2 = __shfl_xor_sync(0xFFFFFFFFu, v2, 1);
            float p3 = __shfl_xor_sync(0xFFFFFFFFu, v3, 1);
            float zi = gp ? p2 : v0;
            float zf = gp ? p3 : v1;
            float zg = gp ? v2 : p0;
            float zo = gp ? v3 : p1;

            float r = rv[mt];
            zi += vbi + r * w5i;
            zf += vbf + r * w5f;
            zg += vbg + r * w5g;
            zo += vbo + r * w5o;

            float cn = fsig(zf) * cj + fsig(zi) * ftanh(zg);
            float hv = fsig(zo) * ftanh(cn);

            int rw = wm * 64 + mt * 16 + (lane >> 2) + (gp ? 8 : 0);
            hsm[rw * 33 + jl] = hv;
        }
    }
    __syncthreads();

    // uint4 fp16 store: 4 iters x 128 threads x 8 halfs
#pragma unroll
    for (int i = 0; i < 4; i++) {
        int slot = tid + i * 128;
        int rw = slot >> 2, c8 = (slot & 3) * 8;
        uint4 o;
        __half* ph = (__half*)&o;
#pragma unroll
        for (int u = 0; u < 8; u += 2) {
            ph[u]     = __float2half_rn(hsm[rw * 33 + c8 + u]);
            ph[u + 1] = __float2half_rn(hsm[rw * 33 + c8 + u + 1]);
        }
        *(uint4*)(g_hf + (size_t)(row0 + rw) * HDIM + j0 + c8) = o;
    }
}

// ---------------------------------------------------------------------------
// heads_mma: 16 rows/block (grid 256), 8 warps x (m16 n8).
// ---------------------------------------------------------------------------
#define H_STA 0
#define H_STB 2048
#define H_STRIDE 10240
#define H_NCH 32
#define H_WV_OFF (3 * H_STRIDE)
#define H_SMEM (3 * H_STRIDE + 8192)

__global__ __launch_bounds__(256, 2) void heads_mma(const float* __restrict__ Wv,
                                                    const float* __restrict__ ba,
                                                    const float* __restrict__ bv,
                                                    float* __restrict__ out) {
    extern __shared__ char smem[];
    uint32_t sb = smem_u32(smem);
    int tid  = threadIdx.x;
    int lane = tid & 31, w = tid >> 5;
    int row0 = blockIdx.x * 16;

    int lr = lane & 7, ls = lane >> 3;
    uint32_t a_row = lr + (ls & 1) * 8;
    uint32_t a_chs = (uint32_t)(ls >> 1);
    uint32_t b_row = w * 8 + lr;
    uint32_t b_chs = (uint32_t)(ls & 1);

    uint32_t pa0 = H_STA + (((a_row * 128) | ((a_row * 16) & 0x70)) ^ (a_chs << 4));
    uint32_t pb0 = H_STB + (((b_row * 128) | ((b_row * 16) & 0x70)) ^ (b_chs << 4));

    uint32_t swA = SWZ128((uint32_t)((tid >> 3) * 128 + (tid & 7) * 16));
    const __half* ph = g_hf + (size_t)(row0 + (tid >> 3)) * HDIM + (tid & 7) * 8;

    float acc[4] = {0.f, 0.f, 0.f, 0.f};

#pragma unroll
    for (int st = 0; st < 2; st++) {
        uint32_t base = sb + st * H_STRIDE;
        if (tid < 128)
            cpa16(base + H_STA + swA, ph + st * 64);
#pragma unroll
        for (int i = 0; i < 2; i++) {
            int slot = tid + i * 256;
            uint32_t sw = SWZ128((uint32_t)((slot >> 3) * 128 + (slot & 7) * 16));
            cpa16(base + H_STB + sw, g_wa + (size_t)(slot >> 3) * HDIM + (slot & 7) * 8 + st * 64);
        }
        CPA_COMMIT();
    }

    for (int t = 0; t < H_NCH; t++) {
        if (t == H_NCH - 1) { CPA_WAIT(0); } else { CPA_WAIT(1); }
        __syncthreads();

        if (t + 2 < H_NCH) {
            uint32_t base = sb + ((t + 2) % 3) * H_STRIDE;
            int kg = (t + 2) * 64;
            if (tid < 128)
                cpa16(base + H_STA + swA, ph + kg);
#pragma unroll
            for (int i = 0; i < 2; i++) {
                int slot = tid + i * 256;
                uint32_t sw = SWZ128((uint32_t)((slot >> 3) * 128 + (slot & 7) * 16));
                cpa16(base + H_STB + sw, g_wa + (size_t)(slot >> 3) * HDIM + (slot & 7) * 8 + kg);
            }
            CPA_COMMIT();
        }

        uint32_t sa = sb + (t % 3) * H_STRIDE;
#pragma unroll
        for (int kb = 0; kb < 8; kb += 2) {
            uint32_t koff = (uint32_t)(kb << 4);
            uint32_t aa[4];
            ldmx4(aa, sa + (pa0 ^ koff));
            uint32_t bb[2];
            ldmx2(bb, sa + (pb0 ^ koff));
            mma16816(acc, aa, bb);
        }
    }
    __syncthreads();

    float* lsm = (float*)smem;
    float* wvs = (float*)(smem + H_WV_OFF);
    {
        int r = lane >> 2;
        int c = w * 8 + (lane & 3) * 2;
        lsm[r * 65 + c]           = acc[0];
        lsm[r * 65 + c + 1]       = acc[1];
        lsm[(r + 8) * 65 + c]     = acc[2];
        lsm[(r + 8) * 65 + c + 1] = acc[3];
    }
#pragma unroll
    for (int i = 0; i < 2; i++) {
        int e = tid + i * 256;
        *(float4*)&wvs[e * 4] = *(const float4*)&Wv[e * 4];
    }
    __syncthreads();

    int rowt = tid >> 4, ag = tid & 15;
    float l[4];
    float m = -INFINITY;
#pragma unroll
    for (int a = 0; a < 4; a++) {
        l[a] = lsm[rowt * 65 + ag * 4 + a] + __ldg(&ba[ag * 4 + a]);
        m = fmaxf(m, l[a]);
    }
#pragma unroll
    for (int off = 8; off > 0; off >>= 1)
        m = fmaxf(m, __shfl_xor_sync(0xFFFFFFFFu, m, off, 16));
    float sum = 0.0f;
#pragma unroll
    for (int a = 0; a < 4; a++) {
        l[a] = __expf(l[a] - m);
        sum += l[a];
    }
#pragma unroll
    for (int off = 8; off > 0; off >>= 1)
        sum += __shfl_xor_sync(0xFFFFFFFFu, sum, off, 16);
    float inv = __fdividef(1.0f, sum);
    int row = row0 + rowt;
#pragma unroll
    for (int a = 0; a < 4; a++)
        out[(size_t)row * 64 + ag * 4 + a] = l[a] * inv;

    float vacc = 0.0f;
    const __half* hrow = g_hf + (size_t)row * HDIM + ag * 128;
#pragma unroll 4
    for (int u = 0; u < 16; u++) {
        uint4 hv = *(const uint4*)(hrow + u * 8);
        __half2* h2 = (__half2*)&hv;
        int kb = ag * 128 + u * 8;
#pragma unroll
        for (int p = 0; p < 4; p++) {
            float2 f = __half22float2(h2[p]);
            vacc += f.x * wvs[kb + p * 2];
            vacc += f.y * wvs[kb + p * 2 + 1];
        }
    }
#pragma unroll
    for (int off = 8; off > 0; off >>= 1)
        vacc += __shfl_xor_sync(0xFFFFFFFFu, vacc, off, 16);
    if (ag == 0)
        out[(size_t)BATCH * 64 + row] = vacc + __ldg(&bv[0]);
}

// ---------------------------------------------------------------------------
extern "C" void kernel_launch(void* const* d_in, const int* in_sizes, int n_in,
                              void* d_out, int out_size) {
    const float* s      = (const float*)d_in[0];
    const float* a_prev = (const float*)d_in[1];
    const float* r_prev = (const float*)d_in[2];
    const float* h      = (const float*)d_in[3];
    const float* c      = (const float*)d_in[4];
    const float* Wx     = (const float*)d_in[5];
    const float* Wh     = (const float*)d_in[6];
    const float* bh     = (const float*)d_in[7];
    const float* Wa     = (const float*)d_in[8];
    const float* ba     = (const float*)d_in[9];
    const float* Wv     = (const float*)d_in[10];
    const float* bv     = (const float*)d_in[11];
    float* out = (float*)d_out;

    static bool attr_set = false;
    if (!attr_set) {
        cudaFuncSetAttribute(lstm_mma, cudaFuncAttributeMaxDynamicSharedMemorySize, SMEM_SZ);
        cudaFuncSetAttribute(heads_mma, cudaFuncAttributeMaxDynamicSharedMemorySize, H_SMEM);
        attr_set = true;
    }

    prep<<<PREP_BLOCKS, 256>>>(s, a_prev, h, Wh, Wx, Wa);
    lstm_mma<<<dim3(HDIM / 32, BATCH / 128), 128, SMEM_SZ>>>(
        c, r_prev, Wx + (size_t)(KDIM - 1) * FOURH, bh);
    heads_mma<<<BATCH / 16, 256, H_SMEM>>>(Wv, ba, bv, out);
}